// round 2
// baseline (speedup 1.0000x reference)
#include <cuda_runtime.h>

#define CCH 32
#define HH  256
#define WW  512
#define KK  10
#define HWPIX (HH*WW)

// Transposed [H,W,C] copies (channels contiguous) — static scratch, no allocs.
__device__ float g_left_t[HWPIX * CCH];
__device__ float g_right_t[HWPIX * CCH];

// [C,H,W] -> [H,W,C] for both feature maps in one kernel.
// Block (32,32): read coalesced over w (tx), write coalesced over c (tx).
__global__ void transpose_chw_hwc(const float* __restrict__ left,
                                  const float* __restrict__ right) {
    __shared__ float tile[2][32][33];
    const int h  = blockIdx.y;
    const int w0 = blockIdx.x * 32;
    const int tx = threadIdx.x, ty = threadIdx.y;
    // read phase: c = ty, w = w0 + tx  (consecutive tx -> consecutive gmem)
    tile[0][ty][tx] = left [ty * HWPIX + h * WW + w0 + tx];
    tile[1][ty][tx] = right[ty * HWPIX + h * WW + w0 + tx];
    __syncthreads();
    // write phase: c = tx, w = w0 + ty (consecutive tx -> consecutive gmem)
    const int o = (h * WW + w0 + ty) * CCH + tx;
    g_left_t [o] = tile[0][tx][ty];
    g_right_t[o] = tile[1][tx][ty];
}

// Warp-per-pixel, channel-per-lane.
__global__ __launch_bounds__(256) void eval_kernel(
    const float* __restrict__ offx,
    const float* __restrict__ offy,
    float* __restrict__ out)
{
    const int lane = threadIdx.x & 31;
    const int pix  = blockIdx.x * (blockDim.x >> 5) + (threadIdx.x >> 5);
    const int h = pix >> 9;       // / WW
    const int w = pix & (WW - 1);

    const float leftv = g_left_t[pix * CCH + lane];

    // lanes 0..9 hold offset_x[k], lanes 10..19 hold offset_y[k]
    float offv = 0.0f;
    if (lane < KK)            offv = offx[lane * HWPIX + pix];
    else if (lane < 2 * KK)   offv = offy[(lane - KK) * HWPIX + pix];

    const float wf = (float)WW, hf = (float)HH;
    float s[KK];

    #pragma unroll
    for (int k = 0; k < KK; k++) {
        const float ox_k = __shfl_sync(0xffffffffu, offv, k);
        const float oy_k = __shfl_sync(0xffffffffu, offv, k + KK);

        // Replicate reference arithmetic exactly (clip -> normalize -> unnormalize)
        float rx = fminf(fmaxf((float)w - ox_k, 0.0f), wf - 1.0f);
        float ry = fminf(fmaxf((float)h - oy_k, 0.0f), hf - 1.0f);
        float gx = (rx - wf * 0.5f) / (wf * 0.5f);
        float gy = (ry - hf * 0.5f) / (hf * 0.5f);
        float ix = ((gx + 1.0f) * wf - 1.0f) * 0.5f;
        float iy = ((gy + 1.0f) * hf - 1.0f) * 0.5f;

        const float x0f = floorf(ix), y0f = floorf(iy);
        const int x0 = (int)x0f, y0 = (int)y0f;
        const int x1 = x0 + 1,   y1 = y0 + 1;
        const float wx1 = ix - x0f, wx0 = 1.0f - wx1;
        const float wy1 = iy - y0f, wy0 = 1.0f - wy1;

        const bool vx0 = (x0 >= 0) && (x0 < WW);
        const bool vx1 = (x1 >= 0) && (x1 < WW);
        const bool vy0 = (y0 >= 0) && (y0 < HH);
        const bool vy1 = (y1 >= 0) && (y1 < HH);

        float g00 = 0.f, g01 = 0.f, g10 = 0.f, g11 = 0.f;
        if (vy0) {
            const float* row = g_right_t + (size_t)(y0 * WW) * CCH;
            if (vx0) g00 = row[x0 * CCH + lane];   // 128B-aligned line, 1 wavefront
            if (vx1) g01 = row[x1 * CCH + lane];
        }
        if (vy1) {
            const float* row = g_right_t + (size_t)(y1 * WW) * CCH;
            if (vx0) g10 = row[x0 * CCH + lane];
            if (vx1) g11 = row[x1 * CCH + lane];
        }

        const float samp = wy0 * (wx0 * g00 + wx1 * g01)
                         + wy1 * (wx0 * g10 + wx1 * g11);
        float d = fabsf(leftv - samp);

        // warp sum over channels
        #pragma unroll
        for (int off = 16; off; off >>= 1)
            d += __shfl_xor_sync(0xffffffffu, d, off);

        s[k] = d * (-10000.0f / 32.0f);   // mean * (-TEMPERATURE)
    }

    // softmax over K (computed redundantly in every lane)
    float m = s[0];
    #pragma unroll
    for (int k = 1; k < KK; k++) m = fmaxf(m, s[k]);
    float denom = 0.0f;
    #pragma unroll
    for (int k = 0; k < KK; k++) { s[k] = __expf(s[k] - m); denom += s[k]; }
    const float inv = 1.0f / denom;

    float ox_acc = 0.0f, oy_acc = 0.0f;
    #pragma unroll
    for (int k = 0; k < KK; k++) {
        const float wk = s[k] * inv;
        ox_acc += __shfl_sync(0xffffffffu, offv, k)      * wk;
        oy_acc += __shfl_sync(0xffffffffu, offv, k + KK) * wk;
    }

    if (lane == 0) {
        out[pix]         = ox_acc;
        out[HWPIX + pix] = oy_acc;
    }
}

extern "C" void kernel_launch(void* const* d_in, const int* in_sizes, int n_in,
                              void* d_out, int out_size) {
    const float* left  = (const float*)d_in[0];
    const float* right = (const float*)d_in[1];
    const float* offx  = (const float*)d_in[2];
    const float* offy  = (const float*)d_in[3];
    float* out = (float*)d_out;

    dim3 tb(32, 32);
    dim3 tg(WW / 32, HH);
    transpose_chw_hwc<<<tg, tb>>>(left, right);

    // 8 warps (8 pixels) per block
    const int warps_per_block = 8;
    const int blocks = HWPIX / warps_per_block;   // 16384
    eval_kernel<<<blocks, warps_per_block * 32>>>(offx, offy, out);
}

// round 3
// speedup vs baseline: 2.4571x; 2.4571x over previous
#include <cuda_runtime.h>

#define CCH 32
#define HH  256
#define WW  512
#define KK  10
#define HWPIX (HH*WW)

// Transposed [H,W,C] copy of right (channels contiguous) — static scratch.
__device__ float g_right_t[HWPIX * CCH];

// [C,H,W] -> [H,W,C] for right only.
__global__ void transpose_chw_hwc(const float* __restrict__ right) {
    __shared__ float tile[32][33];
    const int h  = blockIdx.y;
    const int w0 = blockIdx.x * 32;
    const int tx = threadIdx.x, ty = threadIdx.y;
    tile[ty][tx] = right[ty * HWPIX + h * WW + w0 + tx];
    __syncthreads();
    g_right_t[(h * WW + w0 + ty) * CCH + tx] = tile[tx][ty];
}

// Broadcast offset plane p (0..9 = ox[k], 10..19 = oy[k]) within 8-lane group.
// p is compile-time constant under full unroll; register select folds.
#define BCAST(p) __shfl_sync(0xffffffffu, ((p) < 8 ? o0 : ((p) < 16 ? o1 : o2)), \
                             (lane & 24) | ((p) & 7))

__global__ __launch_bounds__(256) void eval_kernel(
    const float* __restrict__ left,
    const float* __restrict__ offx,
    const float* __restrict__ offy,
    float* __restrict__ out)
{
    const int lane = threadIdx.x & 31;
    const int j    = lane & 7;                      // lane within pixel-group
    const int warp = threadIdx.x >> 5;
    const int pix  = blockIdx.x * 32 + warp * 4 + (lane >> 3);
    const int h = pix >> 9;
    const int w = pix & (WW - 1);

    // left channels 4j..4j+3 (strided scalar loads from original [C,H,W])
    const float lv0 = left[(4*j + 0) * HWPIX + pix];
    const float lv1 = left[(4*j + 1) * HWPIX + pix];
    const float lv2 = left[(4*j + 2) * HWPIX + pix];
    const float lv3 = left[(4*j + 3) * HWPIX + pix];

    // 20 offset planes distributed over the 8-lane group: lane j holds planes j, j+8, j+16
    const float o0 = offx[j * HWPIX + pix];
    const float o1 = (j < 2) ? offx[(j + 8) * HWPIX + pix]
                             : offy[(j - 2) * HWPIX + pix];
    const float o2 = (j < 4) ? offy[(j + 6) * HWPIX + pix] : 0.0f;

    const float4* __restrict__ rt = (const float4*)g_right_t;
    const float wf = (float)WW, hf = (float)HH;
    float s[KK];

    #pragma unroll
    for (int k = 0; k < KK; k++) {
        const float ox_k = BCAST(k);
        const float oy_k = BCAST(k + KK);

        // clip->normalize->unnormalize == rx-0.5 exactly in fp32
        const float rx = fminf(fmaxf((float)w - ox_k, 0.0f), wf - 1.0f);
        const float ry = fminf(fmaxf((float)h - oy_k, 0.0f), hf - 1.0f);
        const float ix = rx - 0.5f;
        const float iy = ry - 0.5f;

        const float x0f = floorf(ix), y0f = floorf(iy);
        const int x0 = (int)x0f, y0 = (int)y0f;          // x0 in [-1,510], y0 in [-1,254]
        const float wx1 = ix - x0f;
        const float wy1 = iy - y0f;
        float wx0 = 1.0f - wx1;
        float wy0 = 1.0f - wy1;
        if (x0 < 0) wx0 = 0.0f;                          // only low edge can be invalid
        if (y0 < 0) wy0 = 0.0f;
        const int x0c = max(x0, 0), y0c = max(y0, 0);
        const int x1 = x0 + 1,      y1 = y0 + 1;         // always in range

        const float w00 = wx0 * wy0, w01 = wx1 * wy0;
        const float w10 = wx0 * wy1, w11 = wx1 * wy1;

        // 4 unconditional 128B gathers (channels 4j..4j+3 of each corner)
        const float4 g00 = rt[(y0c * WW + x0c) * 8 + j];
        const float4 g01 = rt[(y0c * WW + x1 ) * 8 + j];
        const float4 g10 = rt[(y1  * WW + x0c) * 8 + j];
        const float4 g11 = rt[(y1  * WW + x1 ) * 8 + j];

        float d;
        {
            float t0 = w00*g00.x + w01*g01.x + w10*g10.x + w11*g11.x;
            float t1 = w00*g00.y + w01*g01.y + w10*g10.y + w11*g11.y;
            float t2 = w00*g00.z + w01*g01.z + w10*g10.z + w11*g11.z;
            float t3 = w00*g00.w + w01*g01.w + w10*g10.w + w11*g11.w;
            d = fabsf(lv0 - t0) + fabsf(lv1 - t1) + fabsf(lv2 - t2) + fabsf(lv3 - t3);
        }

        // reduce over the 8-lane group (serves all 4 pixels of the warp at once)
        d += __shfl_xor_sync(0xffffffffu, d, 4);
        d += __shfl_xor_sync(0xffffffffu, d, 2);
        d += __shfl_xor_sync(0xffffffffu, d, 1);

        s[k] = d * (-10000.0f / 32.0f);
    }

    // softmax over K (redundant per lane; cheap)
    float m = s[0];
    #pragma unroll
    for (int k = 1; k < KK; k++) m = fmaxf(m, s[k]);
    float denom = 0.0f;
    #pragma unroll
    for (int k = 0; k < KK; k++) { s[k] = __expf(s[k] - m); denom += s[k]; }
    const float inv = 1.0f / denom;

    float ox_acc = 0.0f, oy_acc = 0.0f;
    #pragma unroll
    for (int k = 0; k < KK; k++) {
        const float wk = s[k] * inv;
        ox_acc += BCAST(k)      * wk;
        oy_acc += BCAST(k + KK) * wk;
    }

    if (j == 0) {
        out[pix]         = ox_acc;
        out[HWPIX + pix] = oy_acc;
    }
}

extern "C" void kernel_launch(void* const* d_in, const int* in_sizes, int n_in,
                              void* d_out, int out_size) {
    const float* left  = (const float*)d_in[0];
    const float* right = (const float*)d_in[1];
    const float* offx  = (const float*)d_in[2];
    const float* offy  = (const float*)d_in[3];
    float* out = (float*)d_out;

    dim3 tb(32, 32);
    dim3 tg(WW / 32, HH);
    transpose_chw_hwc<<<tg, tb>>>(right);

    // 256 threads = 8 warps = 32 pixels per block
    eval_kernel<<<HWPIX / 32, 256>>>(left, offx, offy, out);
}